// round 1
// baseline (speedup 1.0000x reference)
#include <cuda_runtime.h>

#define NB 4
#define NT 2048
#define NC 1024
#define NH 16
#define ND 64

// Scratch: Q,K,V in [B,H,T,D] layout (device globals: allocation-free).
__device__ float g_q[NB*NH*NT*ND];
__device__ float g_k[NB*NH*NT*ND];
__device__ float g_v[NB*NH*NT*ND];

// ---------------------------------------------------------------------------
// QKV projection: out = x @ W^T + b, scattered to [B,H,T,D].
// grid = (NC/64, (NB*NT)/64, 3), block = 256.
// 64x64 output tile per block, BK=16, k-major transposed smem tiles.
// ---------------------------------------------------------------------------
__global__ __launch_bounds__(256) void qkv_proj(
    const float* __restrict__ x,
    const float* __restrict__ Wq, const float* __restrict__ bq,
    const float* __restrict__ Wk, const float* __restrict__ bk,
    const float* __restrict__ Wv, const float* __restrict__ bv)
{
    __shared__ float At[16*64];   // At[k][m]
    __shared__ float Bt[16*64];   // Bt[k][n]

    const int z = blockIdx.z;
    const float* __restrict__ W    = (z == 0) ? Wq : ((z == 1) ? Wk : Wv);
    const float* __restrict__ bias = (z == 0) ? bq : ((z == 1) ? bk : bv);
    float* __restrict__ dst        = (z == 0) ? g_q : ((z == 1) ? g_k : g_v);
    const float scale = (z == 0) ? 0.125f : 1.0f;   // q pre-scaled by 1/sqrt(D)

    const int tid = threadIdx.x;
    const int m0 = blockIdx.y * 64;
    const int n0 = blockIdx.x * 64;
    const int ty = tid >> 4, tx = tid & 15;
    const int lr = tid >> 2;            // 0..63
    const int lc = (tid & 3) * 4;       // 0,4,8,12

    float acc[4][4] = {};

    for (int k0 = 0; k0 < NC; k0 += 16) {
        float4 va = *(const float4*)&x[(m0 + lr) * NC + k0 + lc];
        float4 vb = *(const float4*)&W[(n0 + lr) * NC + k0 + lc];
        __syncthreads();
        At[(lc+0)*64 + lr] = va.x; At[(lc+1)*64 + lr] = va.y;
        At[(lc+2)*64 + lr] = va.z; At[(lc+3)*64 + lr] = va.w;
        Bt[(lc+0)*64 + lr] = vb.x; Bt[(lc+1)*64 + lr] = vb.y;
        Bt[(lc+2)*64 + lr] = vb.z; Bt[(lc+3)*64 + lr] = vb.w;
        __syncthreads();

        #pragma unroll 16
        for (int kk = 0; kk < 16; kk++) {
            float4 a4 = *(const float4*)&At[kk*64 + ty*4];
            float4 b4 = *(const float4*)&Bt[kk*64 + tx*4];
            float a[4] = {a4.x, a4.y, a4.z, a4.w};
            float b[4] = {b4.x, b4.y, b4.z, b4.w};
            #pragma unroll
            for (int ii = 0; ii < 4; ii++)
                #pragma unroll
                for (int jj = 0; jj < 4; jj++)
                    acc[ii][jj] += a[ii] * b[jj];
        }
    }

    // Epilogue: add bias, scale, scatter to [B,H,T,D]. h == blockIdx.x since
    // the 64-wide n-tile is exactly one head.
    float4 bv4 = *(const float4*)&bias[n0 + tx*4];
    const float bias4[4] = {bv4.x, bv4.y, bv4.z, bv4.w};
    const int h = blockIdx.x;
    #pragma unroll
    for (int ii = 0; ii < 4; ii++) {
        int m = m0 + ty*4 + ii;
        int b = m >> 11;          // / NT
        int t = m & (NT - 1);
        float4 o;
        o.x = (acc[ii][0] + bias4[0]) * scale;
        o.y = (acc[ii][1] + bias4[1]) * scale;
        o.z = (acc[ii][2] + bias4[2]) * scale;
        o.w = (acc[ii][3] + bias4[3]) * scale;
        *(float4*)&dst[((b*NH + h)*NT + t)*ND + tx*4] = o;
    }
}

// ---------------------------------------------------------------------------
// Flash attention: grid = (NT/64, NB*NH), block = 256, dynamic smem.
// Per block: Q tile [64,64] fixed; stream 64-key chunks; online softmax.
// ---------------------------------------------------------------------------
#define SS_STRIDE 65   // padded score rows -> conflict-free row-wise softmax

__global__ __launch_bounds__(256) void attn_kernel(
    const int* __restrict__ mask, float* __restrict__ out)
{
    extern __shared__ float sm[];
    float* Qt  = sm;            // [64 d][64 q]   4096
    float* Kt  = sm + 4096;     // [64 d][64 key] 4096
    float* Vs  = sm + 8192;     // [64 key][64 d] 4096
    float* Ss  = sm + 12288;    // [64 q][65]     4160
    float* red = sm + 16448;    // [4][64]        256
    float* m_s = sm + 16704;    // 64
    float* l_s = sm + 16768;    // 64
    float* al  = sm + 16832;    // 64
    float* nm  = sm + 16896;    // 64
    int*   msk = (int*)(sm + 16960); // 64
    // total 17024 floats = 68096 bytes

    const int tid = threadIdx.x;
    const int bh  = blockIdx.y;
    const int b   = bh >> 4;
    const int h   = bh & 15;
    const int q0  = blockIdx.x * 64;
    const int ty = tid >> 4, tx = tid & 15;
    const int lr = tid >> 2;
    const int lc0 = (tid & 3) * 4;

    const float* __restrict__ qbase = g_q + (bh*NT + q0) * ND;
    const float* __restrict__ kbase = g_k + bh*NT*ND;
    const float* __restrict__ vbase = g_v + bh*NT*ND;
    const int*   __restrict__ mbase = mask + b*NT;

    // Load Q tile transposed: Qt[d][q]
    #pragma unroll
    for (int p = 0; p < 4; p++) {
        int c = lc0 + p*16;
        float4 v = *(const float4*)&qbase[lr*ND + c];
        Qt[(c+0)*64 + lr] = v.x; Qt[(c+1)*64 + lr] = v.y;
        Qt[(c+2)*64 + lr] = v.z; Qt[(c+3)*64 + lr] = v.w;
    }
    if (tid < 64) { m_s[tid] = -1e30f; l_s[tid] = 0.0f; }

    float O[4][4] = {};

    for (int k0 = 0; k0 < NT; k0 += 64) {
        // Stage K (transposed) and V (natural) for this chunk
        float4 vk[4], vv[4];
        #pragma unroll
        for (int p = 0; p < 4; p++) {
            int c = lc0 + p*16;
            vk[p] = *(const float4*)&kbase[(k0 + lr)*ND + c];
            vv[p] = *(const float4*)&vbase[(k0 + lr)*ND + c];
        }
        __syncthreads();   // previous chunk fully consumed (and Q/init visible)
        #pragma unroll
        for (int p = 0; p < 4; p++) {
            int c = lc0 + p*16;
            Kt[(c+0)*64 + lr] = vk[p].x; Kt[(c+1)*64 + lr] = vk[p].y;
            Kt[(c+2)*64 + lr] = vk[p].z; Kt[(c+3)*64 + lr] = vk[p].w;
            *(float4*)&Vs[lr*64 + c] = vv[p];
        }
        if (tid < 64) msk[tid] = mbase[k0 + tid];
        __syncthreads();

        // S = Q @ K^T  (4x4 per thread; rows i <- ty, keys j <- tx)
        float s[4][4] = {};
        #pragma unroll 16
        for (int kk = 0; kk < 64; kk++) {
            float4 a4 = *(const float4*)&Qt[kk*64 + ty*4];
            float4 b4 = *(const float4*)&Kt[kk*64 + tx*4];
            float a[4] = {a4.x, a4.y, a4.z, a4.w};
            float bb[4] = {b4.x, b4.y, b4.z, b4.w};
            #pragma unroll
            for (int ii = 0; ii < 4; ii++)
                #pragma unroll
                for (int jj = 0; jj < 4; jj++)
                    s[ii][jj] += a[ii] * bb[jj];
        }

        // Masked store (exact reference semantics: masked -> -1e30)
        #pragma unroll
        for (int jj = 0; jj < 4; jj++) {
            bool keep = msk[tx*4 + jj] > 0;
            #pragma unroll
            for (int ii = 0; ii < 4; ii++)
                Ss[(ty*4 + ii)*SS_STRIDE + tx*4 + jj] = keep ? s[ii][jj] : -1e30f;
        }
        __syncthreads();

        // Online softmax. thread -> (row ri, 16-key segment sg)
        const int ri = tid >> 2;
        const int sg = (tid & 3) * 16;
        float pm = -1e30f;
        #pragma unroll
        for (int jj = 0; jj < 16; jj++)
            pm = fmaxf(pm, Ss[ri*SS_STRIDE + sg + jj]);
        red[(tid & 3)*64 + ri] = pm;
        __syncthreads();
        if (tid < 64) {
            float cm = fmaxf(fmaxf(red[tid], red[64+tid]),
                             fmaxf(red[128+tid], red[192+tid]));
            float mold = m_s[tid];
            float mnew = fmaxf(mold, cm);
            m_s[tid] = mnew;
            nm[tid]  = mnew;
            al[tid]  = __expf(mold - mnew);
        }
        __syncthreads();
        float mrow = nm[ri];
        float psum = 0.0f;
        #pragma unroll
        for (int jj = 0; jj < 16; jj++) {
            float p = __expf(Ss[ri*SS_STRIDE + sg + jj] - mrow);
            Ss[ri*SS_STRIDE + sg + jj] = p;
            psum += p;
        }
        red[(tid & 3)*64 + ri] = psum;
        __syncthreads();
        if (tid < 64)
            l_s[tid] = l_s[tid]*al[tid]
                     + red[tid] + red[64+tid] + red[128+tid] + red[192+tid];

        // Rescale O and accumulate P @ V
        float alr[4] = {al[ty*4+0], al[ty*4+1], al[ty*4+2], al[ty*4+3]};
        #pragma unroll
        for (int ii = 0; ii < 4; ii++)
            #pragma unroll
            for (int jj = 0; jj < 4; jj++)
                O[ii][jj] *= alr[ii];

        #pragma unroll 8
        for (int j = 0; j < 64; j++) {
            float4 v4 = *(const float4*)&Vs[j*64 + tx*4];
            float vr[4] = {v4.x, v4.y, v4.z, v4.w};
            float p0 = Ss[(ty*4+0)*SS_STRIDE + j];
            float p1 = Ss[(ty*4+1)*SS_STRIDE + j];
            float p2 = Ss[(ty*4+2)*SS_STRIDE + j];
            float p3 = Ss[(ty*4+3)*SS_STRIDE + j];
            #pragma unroll
            for (int jj = 0; jj < 4; jj++) {
                O[0][jj] += p0 * vr[jj];
                O[1][jj] += p1 * vr[jj];
                O[2][jj] += p2 * vr[jj];
                O[3][jj] += p3 * vr[jj];
            }
        }
        // loop-top barrier covers Kt/Vs/Ss reuse
    }

    __syncthreads();   // l_s final
    #pragma unroll
    for (int ii = 0; ii < 4; ii++) {
        float iv = 1.0f / l_s[ty*4 + ii];
        float4 o;
        o.x = O[ii][0] * iv; o.y = O[ii][1] * iv;
        o.z = O[ii][2] * iv; o.w = O[ii][3] * iv;
        int t = q0 + ty*4 + ii;
        *(float4*)&out[(b*NT + t)*NC + h*ND + tx*4] = o;
    }
}

// ---------------------------------------------------------------------------
extern "C" void kernel_launch(void* const* d_in, const int* in_sizes, int n_in,
                              void* d_out, int out_size)
{
    const float* x  = (const float*)d_in[0];
    const int* mask = (const int*)  d_in[1];
    const float* Wq = (const float*)d_in[2];
    const float* bq = (const float*)d_in[3];
    const float* Wk = (const float*)d_in[4];
    const float* bk = (const float*)d_in[5];
    const float* Wv = (const float*)d_in[6];
    const float* bv = (const float*)d_in[7];
    float* out = (float*)d_out;

    // QKV projections (z selects Q/K/V)
    dim3 gproj(NC/64, (NB*NT)/64, 3);
    qkv_proj<<<gproj, 256>>>(x, Wq, bq, Wk, bk, Wv, bv);

    // Attention (dynamic smem 68096 B > 48 KB default -> opt in every call;
    // immediate API, graph-capture safe, deterministic)
    const int smem_bytes = 17024 * 4;
    cudaFuncSetAttribute(attn_kernel,
                         cudaFuncAttributeMaxDynamicSharedMemorySize, smem_bytes);
    attn_kernel<<<dim3(NT/64, NB*NH), 256, smem_bytes>>>(mask, out);
}

// round 2
// speedup vs baseline: 1.2666x; 1.2666x over previous
#include <cuda_runtime.h>

#define NB 4
#define NT 2048
#define NC 1024
#define NH 16
#define ND 64

// Scratch: Q,K,V in [B,H,T,D] layout (device globals: allocation-free).
__device__ float g_q[NB*NH*NT*ND];
__device__ float g_k[NB*NH*NT*ND];
__device__ float g_v[NB*NH*NT*ND];

// ---------------------------------------------------------------------------
// QKV projection: out = x @ W^T + b, scattered to [B,H,T,D].
// grid = (NC/128, (NB*NT)/128, 3), block = 256. 128x128 tile, 8x8/thread
// (as 2x2 blocks of 4x4 fragments so every LDS.128 is phase-conflict-free).
// ---------------------------------------------------------------------------
#define BMP 132   // padded k-row stride for At/Bt

__global__ __launch_bounds__(256) void qkv_proj(
    const float* __restrict__ x,
    const float* __restrict__ Wq, const float* __restrict__ bq,
    const float* __restrict__ Wk, const float* __restrict__ bk,
    const float* __restrict__ Wv, const float* __restrict__ bv)
{
    __shared__ float At[16*BMP];   // At[k][m]
    __shared__ float Bt[16*BMP];   // Bt[k][n]

    const int z = blockIdx.z;
    const float* __restrict__ W    = (z == 0) ? Wq : ((z == 1) ? Wk : Wv);
    const float* __restrict__ bias = (z == 0) ? bq : ((z == 1) ? bk : bv);
    float* __restrict__ dst        = (z == 0) ? g_q : ((z == 1) ? g_k : g_v);
    const float scale = (z == 0) ? 0.125f : 1.0f;   // q pre-scaled by 1/sqrt(D)

    const int tid = threadIdx.x;
    const int m0 = blockIdx.y * 128;
    const int n0 = blockIdx.x * 128;
    const int ty = tid >> 4, tx = tid & 15;
    const int sr = tid >> 2;            // 0..63
    const int sc = (tid & 3) * 4;       // 0,4,8,12

    float acc[8][8] = {};

    for (int k0 = 0; k0 < NC; k0 += 16) {
        float4 va0 = *(const float4*)&x[(m0 + sr     ) * NC + k0 + sc];
        float4 va1 = *(const float4*)&x[(m0 + sr + 64) * NC + k0 + sc];
        float4 vb0 = *(const float4*)&W[(n0 + sr     ) * NC + k0 + sc];
        float4 vb1 = *(const float4*)&W[(n0 + sr + 64) * NC + k0 + sc];
        __syncthreads();
        At[(sc+0)*BMP + sr] = va0.x; At[(sc+1)*BMP + sr] = va0.y;
        At[(sc+2)*BMP + sr] = va0.z; At[(sc+3)*BMP + sr] = va0.w;
        At[(sc+0)*BMP + sr+64] = va1.x; At[(sc+1)*BMP + sr+64] = va1.y;
        At[(sc+2)*BMP + sr+64] = va1.z; At[(sc+3)*BMP + sr+64] = va1.w;
        Bt[(sc+0)*BMP + sr] = vb0.x; Bt[(sc+1)*BMP + sr] = vb0.y;
        Bt[(sc+2)*BMP + sr] = vb0.z; Bt[(sc+3)*BMP + sr] = vb0.w;
        Bt[(sc+0)*BMP + sr+64] = vb1.x; Bt[(sc+1)*BMP + sr+64] = vb1.y;
        Bt[(sc+2)*BMP + sr+64] = vb1.z; Bt[(sc+3)*BMP + sr+64] = vb1.w;
        __syncthreads();

        #pragma unroll 16
        for (int kk = 0; kk < 16; kk++) {
            float4 a0 = *(const float4*)&At[kk*BMP + ty*4];
            float4 a1 = *(const float4*)&At[kk*BMP + 64 + ty*4];
            float4 b0 = *(const float4*)&Bt[kk*BMP + tx*4];
            float4 b1 = *(const float4*)&Bt[kk*BMP + 64 + tx*4];
            float a[8] = {a0.x,a0.y,a0.z,a0.w, a1.x,a1.y,a1.z,a1.w};
            float b[8] = {b0.x,b0.y,b0.z,b0.w, b1.x,b1.y,b1.z,b1.w};
            #pragma unroll
            for (int ii = 0; ii < 8; ii++)
                #pragma unroll
                for (int jj = 0; jj < 8; jj++)
                    acc[ii][jj] += a[ii] * b[jj];
        }
    }

    // Epilogue: bias, scale, scatter to [B,H,T,D]. n-tile spans 2 heads.
    float4 blo = *(const float4*)&bias[n0 + tx*4];
    float4 bhi = *(const float4*)&bias[n0 + 64 + tx*4];
    const float bs[8] = {blo.x,blo.y,blo.z,blo.w, bhi.x,bhi.y,bhi.z,bhi.w};
    const int h0 = blockIdx.x * 2;
    #pragma unroll
    for (int rh = 0; rh < 2; rh++) {
        #pragma unroll
        for (int ii = 0; ii < 4; ii++) {
            int m = m0 + rh*64 + ty*4 + ii;
            int b = m >> 11;
            int t = m & (NT - 1);
            #pragma unroll
            for (int ch = 0; ch < 2; ch++) {
                int h = h0 + ch;
                float4 o;
                o.x = (acc[rh*4+ii][ch*4+0] + bs[ch*4+0]) * scale;
                o.y = (acc[rh*4+ii][ch*4+1] + bs[ch*4+1]) * scale;
                o.z = (acc[rh*4+ii][ch*4+2] + bs[ch*4+2]) * scale;
                o.w = (acc[rh*4+ii][ch*4+3] + bs[ch*4+3]) * scale;
                *(float4*)&dst[((b*NH + h)*NT + t)*ND + tx*4] = o;
            }
        }
    }
}

// ---------------------------------------------------------------------------
// Flash attention: grid = (NT/64, NB*NH), block = 256.
// Register-resident online softmax (warp shuffles), single P smem pass.
// ---------------------------------------------------------------------------
#define QST 68   // padded stride for Qt/Kt/Ps

__global__ __launch_bounds__(256) void attn_kernel(
    const int* __restrict__ mask, float* __restrict__ out)
{
    extern __shared__ float sm[];
    float* Qt = sm;                  // [64 d][QST] : Qt[d*QST + q]
    float* Kt = sm + 64*QST;         // [64 d][QST] : Kt[d*QST + key]
    float* Vs = Kt + 64*QST;         // [64 key][64 d] natural
    float* Ps = Vs + 64*64;          // [64 row][QST]
    // total = 3*4352 + 4096 = 17152 floats = 68608 bytes

    const int tid = threadIdx.x;
    const int bh  = blockIdx.y;
    const int b   = bh >> 4;
    const int h   = bh & 15;
    const int q0  = blockIdx.x * 64;
    const int ty = tid >> 4, tx = tid & 15;
    const int sr = tid >> 2;
    const int sc = (tid & 3) * 4;

    const float* __restrict__ qbase = g_q + (bh*NT + q0) * ND;
    const float* __restrict__ kbase = g_k + bh*NT*ND;
    const float* __restrict__ vbase = g_v + bh*NT*ND;
    const int*   __restrict__ mbase = mask + b*NT;

    // Load Q tile transposed: Qt[d][q]
    #pragma unroll
    for (int p = 0; p < 4; p++) {
        int c = sc + p*16;
        float4 v = *(const float4*)&qbase[sr*ND + c];
        Qt[(c+0)*QST + sr] = v.x; Qt[(c+1)*QST + sr] = v.y;
        Qt[(c+2)*QST + sr] = v.z; Qt[(c+3)*QST + sr] = v.w;
    }

    // Per-thread softmax state for rows ty*4..ty*4+3 (replicated across tx,
    // kept consistent by shuffle reductions).
    float m_run[4] = {-1e30f,-1e30f,-1e30f,-1e30f};
    float l_run[4] = {0.f,0.f,0.f,0.f};
    float O[4][4] = {};

    for (int k0 = 0; k0 < NT; k0 += 64) {
        // gmem loads (no smem) before the barrier
        float4 vk[4];
        #pragma unroll
        for (int p = 0; p < 4; p++)
            vk[p] = *(const float4*)&kbase[(k0 + sr)*ND + sc + p*16];
        int4 mm = *(const int4*)&mbase[k0 + tx*4];

        __syncthreads();   // all prior-chunk smem reads done
        #pragma unroll
        for (int p = 0; p < 4; p++) {
            int c = sc + p*16;
            Kt[(c+0)*QST + sr] = vk[p].x; Kt[(c+1)*QST + sr] = vk[p].y;
            Kt[(c+2)*QST + sr] = vk[p].z; Kt[(c+3)*QST + sr] = vk[p].w;
        }
        // V: flat conflict-free float4 copy (layout preserved: [key][d])
        #pragma unroll
        for (int p = 0; p < 4; p++) {
            float4 vv = ((const float4*)(vbase + k0*ND))[tid + 256*p];
            ((float4*)Vs)[tid + 256*p] = vv;
        }
        __syncthreads();

        // S = Q @ K^T (4 rows x 4 keys per thread)
        float s[4][4] = {};
        #pragma unroll 16
        for (int kk = 0; kk < 64; kk++) {
            float4 a4 = *(const float4*)&Qt[kk*QST + ty*4];
            float4 b4 = *(const float4*)&Kt[kk*QST + tx*4];
            float a[4] = {a4.x, a4.y, a4.z, a4.w};
            float bb[4] = {b4.x, b4.y, b4.z, b4.w};
            #pragma unroll
            for (int ii = 0; ii < 4; ii++)
                #pragma unroll
                for (int jj = 0; jj < 4; jj++)
                    s[ii][jj] += a[ii] * bb[jj];
        }

        // mask (reference semantics: masked -> -1e30)
        if (mm.x <= 0) { s[0][0]=-1e30f; s[1][0]=-1e30f; s[2][0]=-1e30f; s[3][0]=-1e30f; }
        if (mm.y <= 0) { s[0][1]=-1e30f; s[1][1]=-1e30f; s[2][1]=-1e30f; s[3][1]=-1e30f; }
        if (mm.z <= 0) { s[0][2]=-1e30f; s[1][2]=-1e30f; s[2][2]=-1e30f; s[3][2]=-1e30f; }
        if (mm.w <= 0) { s[0][3]=-1e30f; s[1][3]=-1e30f; s[2][3]=-1e30f; s[3][3]=-1e30f; }

        // row max across this chunk: in-thread then shuffle over the 16 tx
        // owners (they share a half-warp; xor 1/2/4/8 stays inside it).
        float alph[4];
        #pragma unroll
        for (int ii = 0; ii < 4; ii++) {
            float rm = fmaxf(fmaxf(s[ii][0], s[ii][1]), fmaxf(s[ii][2], s[ii][3]));
            rm = fmaxf(rm, __shfl_xor_sync(0xffffffffu, rm, 1));
            rm = fmaxf(rm, __shfl_xor_sync(0xffffffffu, rm, 2));
            rm = fmaxf(rm, __shfl_xor_sync(0xffffffffu, rm, 4));
            rm = fmaxf(rm, __shfl_xor_sync(0xffffffffu, rm, 8));
            float mnew = fmaxf(m_run[ii], rm);
            alph[ii] = __expf(m_run[ii] - mnew);
            m_run[ii] = mnew;
        }

        // p = exp(s - m), row sums, store P (conflict-free float4)
        #pragma unroll
        for (int ii = 0; ii < 4; ii++) {
            float4 p4;
            p4.x = __expf(s[ii][0] - m_run[ii]);
            p4.y = __expf(s[ii][1] - m_run[ii]);
            p4.z = __expf(s[ii][2] - m_run[ii]);
            p4.w = __expf(s[ii][3] - m_run[ii]);
            float ps = (p4.x + p4.y) + (p4.z + p4.w);
            ps += __shfl_xor_sync(0xffffffffu, ps, 1);
            ps += __shfl_xor_sync(0xffffffffu, ps, 2);
            ps += __shfl_xor_sync(0xffffffffu, ps, 4);
            ps += __shfl_xor_sync(0xffffffffu, ps, 8);
            l_run[ii] = l_run[ii] * alph[ii] + ps;
            *(float4*)&Ps[(ty*4 + ii)*QST + tx*4] = p4;
            #pragma unroll
            for (int jj = 0; jj < 4; jj++)
                O[ii][jj] *= alph[ii];
        }
        __syncthreads();   // Ps visible

        // O += P @ V
        #pragma unroll 8
        for (int j = 0; j < 64; j++) {
            float4 v4 = *(const float4*)&Vs[j*64 + tx*4];
            float vr[4] = {v4.x, v4.y, v4.z, v4.w};
            float p0 = Ps[(ty*4+0)*QST + j];
            float p1 = Ps[(ty*4+1)*QST + j];
            float p2 = Ps[(ty*4+2)*QST + j];
            float p3 = Ps[(ty*4+3)*QST + j];
            #pragma unroll
            for (int jj = 0; jj < 4; jj++) {
                O[0][jj] += p0 * vr[jj];
                O[1][jj] += p1 * vr[jj];
                O[2][jj] += p2 * vr[jj];
                O[3][jj] += p3 * vr[jj];
            }
        }
    }

    #pragma unroll
    for (int ii = 0; ii < 4; ii++) {
        float iv = 1.0f / l_run[ii];
        float4 o;
        o.x = O[ii][0] * iv; o.y = O[ii][1] * iv;
        o.z = O[ii][2] * iv; o.w = O[ii][3] * iv;
        int t = q0 + ty*4 + ii;
        *(float4*)&out[(b*NT + t)*NC + h*ND + tx*4] = o;
    }
}

// ---------------------------------------------------------------------------
extern "C" void kernel_launch(void* const* d_in, const int* in_sizes, int n_in,
                              void* d_out, int out_size)
{
    const float* x  = (const float*)d_in[0];
    const int* mask = (const int*)  d_in[1];
    const float* Wq = (const float*)d_in[2];
    const float* bq = (const float*)d_in[3];
    const float* Wk = (const float*)d_in[4];
    const float* bk = (const float*)d_in[5];
    const float* Wv = (const float*)d_in[6];
    const float* bv = (const float*)d_in[7];
    float* out = (float*)d_out;

    dim3 gproj(NC/128, (NB*NT)/128, 3);
    qkv_proj<<<gproj, 256>>>(x, Wq, bq, Wk, bk, Wv, bv);

    const int smem_bytes = (3*64*QST + 64*64) * 4;   // 68608
    cudaFuncSetAttribute(attn_kernel,
                         cudaFuncAttributeMaxDynamicSharedMemorySize, smem_bytes);
    attn_kernel<<<dim3(NT/64, NB*NH), 256, smem_bytes>>>(mask, out);
}

// round 3
// speedup vs baseline: 2.2336x; 1.7635x over previous
#include <cuda_runtime.h>
#include <cstdint>

#define NB 4
#define NT 2048
#define NC 1024
#define NH 16
#define ND 64

// Scratch: Q,K,V in [B,H,T,D] layout (device globals: allocation-free).
__device__ float g_q[NB*NH*NT*ND];
__device__ float g_k[NB*NH*NT*ND];
__device__ float g_v[NB*NH*NT*ND];

// ---------------------------------------------------------------------------
// helpers: tf32 round-to-nearest, f32 bit view, m16n8k8 tf32 mma
// ---------------------------------------------------------------------------
__device__ __forceinline__ float tf32r(float x) {
    uint32_t u;
    asm("cvt.rna.tf32.f32 %0, %1;" : "=r"(u) : "f"(x));
    return __uint_as_float(u);
}
__device__ __forceinline__ uint32_t fau(float x) { return __float_as_uint(x); }

__device__ __forceinline__ void mma_tf32(float d[4], const uint32_t a[4],
                                         const uint32_t b[2]) {
    asm volatile(
        "mma.sync.aligned.m16n8k8.row.col.f32.tf32.tf32.f32 "
        "{%0,%1,%2,%3}, {%4,%5,%6,%7}, {%8,%9}, {%0,%1,%2,%3};"
        : "+f"(d[0]), "+f"(d[1]), "+f"(d[2]), "+f"(d[3])
        : "r"(a[0]), "r"(a[1]), "r"(a[2]), "r"(a[3]), "r"(b[0]), "r"(b[1]));
}

// ---------------------------------------------------------------------------
// QKV projection (fp32, unchanged from R2 — known good, keeps q/k/v exact).
// grid = (NC/128, (NB*NT)/128, 3), block = 256. 128x128 tile, 8x8/thread.
// ---------------------------------------------------------------------------
#define BMP 132

__global__ __launch_bounds__(256) void qkv_proj(
    const float* __restrict__ x,
    const float* __restrict__ Wq, const float* __restrict__ bq,
    const float* __restrict__ Wk, const float* __restrict__ bk,
    const float* __restrict__ Wv, const float* __restrict__ bv)
{
    __shared__ float At[16*BMP];
    __shared__ float Bt[16*BMP];

    const int z = blockIdx.z;
    const float* __restrict__ W    = (z == 0) ? Wq : ((z == 1) ? Wk : Wv);
    const float* __restrict__ bias = (z == 0) ? bq : ((z == 1) ? bk : bv);
    float* __restrict__ dst        = (z == 0) ? g_q : ((z == 1) ? g_k : g_v);
    const float scale = (z == 0) ? 0.125f : 1.0f;

    const int tid = threadIdx.x;
    const int m0 = blockIdx.y * 128;
    const int n0 = blockIdx.x * 128;
    const int ty = tid >> 4, tx = tid & 15;
    const int sr = tid >> 2;
    const int sc = (tid & 3) * 4;

    float acc[8][8] = {};

    for (int k0 = 0; k0 < NC; k0 += 16) {
        float4 va0 = *(const float4*)&x[(m0 + sr     ) * NC + k0 + sc];
        float4 va1 = *(const float4*)&x[(m0 + sr + 64) * NC + k0 + sc];
        float4 vb0 = *(const float4*)&W[(n0 + sr     ) * NC + k0 + sc];
        float4 vb1 = *(const float4*)&W[(n0 + sr + 64) * NC + k0 + sc];
        __syncthreads();
        At[(sc+0)*BMP + sr] = va0.x; At[(sc+1)*BMP + sr] = va0.y;
        At[(sc+2)*BMP + sr] = va0.z; At[(sc+3)*BMP + sr] = va0.w;
        At[(sc+0)*BMP + sr+64] = va1.x; At[(sc+1)*BMP + sr+64] = va1.y;
        At[(sc+2)*BMP + sr+64] = va1.z; At[(sc+3)*BMP + sr+64] = va1.w;
        Bt[(sc+0)*BMP + sr] = vb0.x; Bt[(sc+1)*BMP + sr] = vb0.y;
        Bt[(sc+2)*BMP + sr] = vb0.z; Bt[(sc+3)*BMP + sr] = vb0.w;
        Bt[(sc+0)*BMP + sr+64] = vb1.x; Bt[(sc+1)*BMP + sr+64] = vb1.y;
        Bt[(sc+2)*BMP + sr+64] = vb1.z; Bt[(sc+3)*BMP + sr+64] = vb1.w;
        __syncthreads();

        #pragma unroll 16
        for (int kk = 0; kk < 16; kk++) {
            float4 a0 = *(const float4*)&At[kk*BMP + ty*4];
            float4 a1 = *(const float4*)&At[kk*BMP + 64 + ty*4];
            float4 b0 = *(const float4*)&Bt[kk*BMP + tx*4];
            float4 b1 = *(const float4*)&Bt[kk*BMP + 64 + tx*4];
            float a[8] = {a0.x,a0.y,a0.z,a0.w, a1.x,a1.y,a1.z,a1.w};
            float b[8] = {b0.x,b0.y,b0.z,b0.w, b1.x,b1.y,b1.z,b1.w};
            #pragma unroll
            for (int ii = 0; ii < 8; ii++)
                #pragma unroll
                for (int jj = 0; jj < 8; jj++)
                    acc[ii][jj] += a[ii] * b[jj];
        }
    }

    float4 blo = *(const float4*)&bias[n0 + tx*4];
    float4 bhi = *(const float4*)&bias[n0 + 64 + tx*4];
    const float bs[8] = {blo.x,blo.y,blo.z,blo.w, bhi.x,bhi.y,bhi.z,bhi.w};
    const int h0 = blockIdx.x * 2;
    #pragma unroll
    for (int rh = 0; rh < 2; rh++) {
        #pragma unroll
        for (int ii = 0; ii < 4; ii++) {
            int m = m0 + rh*64 + ty*4 + ii;
            int b = m >> 11;
            int t = m & (NT - 1);
            #pragma unroll
            for (int ch = 0; ch < 2; ch++) {
                int h = h0 + ch;
                float4 o;
                o.x = (acc[rh*4+ii][ch*4+0] + bs[ch*4+0]) * scale;
                o.y = (acc[rh*4+ii][ch*4+1] + bs[ch*4+1]) * scale;
                o.z = (acc[rh*4+ii][ch*4+2] + bs[ch*4+2]) * scale;
                o.w = (acc[rh*4+ii][ch*4+3] + bs[ch*4+3]) * scale;
                *(float4*)&dst[((b*NH + h)*NT + t)*ND + tx*4] = o;
            }
        }
    }
}

// ---------------------------------------------------------------------------
// Flash attention on tf32 tensor cores.
// grid = (NT/128, NB*NH), block = 256 (8 warps, 16 q-rows each).
// Per chunk (64 keys): S = Q@K^T via mma, register softmax (mma accum layout,
// quad shuffles), P->smem (tf32), O += P@V via mma.
// ---------------------------------------------------------------------------
#define QP 68   // stride for Qs/Ks/Ps  -> conflict-free fragment LDS
#define VP 72   // stride for Vs        -> conflict-free B-fragment LDS

__global__ __launch_bounds__(256) void attn_kernel(
    const int* __restrict__ mask, float* __restrict__ out)
{
    extern __shared__ float sm[];
    float* Qs    = sm;              // [128][QP] = 8704
    float* Ps    = sm + 8704;       // [128][QP] = 8704
    float* Ks    = sm + 17408;      // [64][QP]  = 4352
    float* Vs    = sm + 21760;      // [64][VP]  = 4608
    float* maskf = sm + 26368;      // [64]
    // total 26432 floats = 105728 bytes

    const int tid  = threadIdx.x;
    const int warp = tid >> 5;
    const int lane = tid & 31;
    const int g    = lane >> 2;     // groupID (row within 16-row tile)
    const int c    = lane & 3;      // threadID-in-group (k / col pair idx)
    const int wr   = warp * 16;     // warp's q-row base within block

    const int bh = blockIdx.y;
    const int b  = bh >> 4;
    const int h  = bh & 15;
    const int q0 = blockIdx.x * 128;

    const float* __restrict__ qb = g_q + (bh*NT + q0) * ND;
    const float* __restrict__ kb = g_k + bh*NT*ND;
    const float* __restrict__ vb = g_v + bh*NT*ND;
    const int*   __restrict__ mb = mask + b*NT;

    // Stage Q once (tf32-rounded): 128 rows x 64 d
    #pragma unroll
    for (int i = 0; i < 8; i++) {
        int fi = tid + 256*i;            // 0..2047 float4s
        int row = fi >> 4, c4 = (fi & 15) * 4;
        float4 v = *(const float4*)&qb[row*ND + c4];
        float4 w = make_float4(tf32r(v.x), tf32r(v.y), tf32r(v.z), tf32r(v.w));
        *(float4*)&Qs[row*QP + c4] = w;
    }

    float o[8][4] = {};
    float m_run[2] = {-1e30f, -1e30f};
    float l_run[2] = {0.f, 0.f};

    for (int k0 = 0; k0 < NT; k0 += 64) {
        __syncthreads();   // prior chunk's Ks/Vs reads complete
        // Stage K [64][QP], V [64][VP] (tf32-rounded), mask -> additive float
        #pragma unroll
        for (int i = 0; i < 4; i++) {
            int fi = tid + 256*i;        // 0..1023
            int row = fi >> 4, c4 = (fi & 15) * 4;
            float4 v = *(const float4*)&kb[(k0 + row)*ND + c4];
            *(float4*)&Ks[row*QP + c4] =
                make_float4(tf32r(v.x), tf32r(v.y), tf32r(v.z), tf32r(v.w));
            float4 u = *(const float4*)&vb[(k0 + row)*ND + c4];
            *(float4*)&Vs[row*VP + c4] =
                make_float4(tf32r(u.x), tf32r(u.y), tf32r(u.z), tf32r(u.w));
        }
        if (tid < 64) maskf[tid] = (mb[k0 + tid] > 0) ? 0.0f : -1e30f;
        __syncthreads();

        // ---- S = Q @ K^T  (per warp: 16 rows x 64 keys) ----
        float s[8][4] = {};
        #pragma unroll
        for (int kt = 0; kt < 8; kt++) {
            const int k = kt*8;
            uint32_t a[4];
            const float* qr = &Qs[(wr + g)*QP + k];
            a[0] = fau(qr[c]);          a[1] = fau(qr[8*QP + c]);
            a[2] = fau(qr[c + 4]);      a[3] = fau(qr[8*QP + c + 4]);
            #pragma unroll
            for (int nt = 0; nt < 8; nt++) {
                uint32_t bb[2];
                const float* kr = &Ks[(nt*8 + g)*QP + k];
                bb[0] = fau(kr[c]); bb[1] = fau(kr[c + 4]);
                mma_tf32(s[nt], a, bb);
            }
        }

        // additive mask (reference semantics: masked -> -1e30)
        #pragma unroll
        for (int nt = 0; nt < 8; nt++) {
            float2 mf = *(const float2*)&maskf[nt*8 + 2*c];
            s[nt][0] += mf.x; s[nt][1] += mf.y;
            s[nt][2] += mf.x; s[nt][3] += mf.y;
        }

        // ---- online softmax in mma accumulator layout ----
        // regs [0],[1] -> row g; [2],[3] -> row g+8. Row spread over quad
        // lanes (xor 1,2 reductions stay inside the quad).
        float alpha[2];
        #pragma unroll
        for (int rh = 0; rh < 2; rh++) {
            float rm = -1e30f;
            #pragma unroll
            for (int nt = 0; nt < 8; nt++)
                rm = fmaxf(rm, fmaxf(s[nt][rh*2], s[nt][rh*2+1]));
            rm = fmaxf(rm, __shfl_xor_sync(0xffffffffu, rm, 1));
            rm = fmaxf(rm, __shfl_xor_sync(0xffffffffu, rm, 2));
            float mnew = fmaxf(m_run[rh], rm);
            alpha[rh] = __expf(m_run[rh] - mnew);
            m_run[rh] = mnew;
            float rs = 0.f;
            #pragma unroll
            for (int nt = 0; nt < 8; nt++) {
                float p0 = __expf(s[nt][rh*2]   - mnew);
                float p1 = __expf(s[nt][rh*2+1] - mnew);
                s[nt][rh*2] = p0; s[nt][rh*2+1] = p1;
                rs += p0 + p1;
            }
            rs += __shfl_xor_sync(0xffffffffu, rs, 1);
            rs += __shfl_xor_sync(0xffffffffu, rs, 2);
            l_run[rh] = l_run[rh]*alpha[rh] + rs;
        }

        // rescale O
        #pragma unroll
        for (int nt = 0; nt < 8; nt++) {
            o[nt][0] *= alpha[0]; o[nt][1] *= alpha[0];
            o[nt][2] *= alpha[1]; o[nt][3] *= alpha[1];
        }

        // ---- P -> smem (tf32-rounded); warp-private rows -> syncwarp ----
        #pragma unroll
        for (int nt = 0; nt < 8; nt++) {
            float2 lo = make_float2(tf32r(s[nt][0]), tf32r(s[nt][1]));
            float2 hi = make_float2(tf32r(s[nt][2]), tf32r(s[nt][3]));
            *(float2*)&Ps[(wr + g    )*QP + nt*8 + 2*c] = lo;
            *(float2*)&Ps[(wr + g + 8)*QP + nt*8 + 2*c] = hi;
        }
        __syncwarp();

        // ---- O += P @ V ----
        #pragma unroll
        for (int kt = 0; kt < 8; kt++) {
            const int k = kt*8;
            uint32_t a[4];
            const float* pr = &Ps[(wr + g)*QP + k];
            a[0] = fau(pr[c]);          a[1] = fau(pr[8*QP + c]);
            a[2] = fau(pr[c + 4]);      a[3] = fau(pr[8*QP + c + 4]);
            #pragma unroll
            for (int nt = 0; nt < 8; nt++) {
                uint32_t bb[2];
                bb[0] = fau(Vs[(k + c    )*VP + nt*8 + g]);
                bb[1] = fau(Vs[(k + c + 4)*VP + nt*8 + g]);
                mma_tf32(o[nt], a, bb);
            }
        }
    }

    // epilogue: normalize, store
    const float inv0 = 1.0f / l_run[0];
    const float inv1 = 1.0f / l_run[1];
    const int t0 = q0 + wr + g;
    float* ob0 = out + (b*NT + t0    )*NC + h*ND;
    float* ob1 = out + (b*NT + t0 + 8)*NC + h*ND;
    #pragma unroll
    for (int nt = 0; nt < 8; nt++) {
        *(float2*)&ob0[nt*8 + 2*c] = make_float2(o[nt][0]*inv0, o[nt][1]*inv0);
        *(float2*)&ob1[nt*8 + 2*c] = make_float2(o[nt][2]*inv1, o[nt][3]*inv1);
    }
}

// ---------------------------------------------------------------------------
extern "C" void kernel_launch(void* const* d_in, const int* in_sizes, int n_in,
                              void* d_out, int out_size)
{
    const float* x  = (const float*)d_in[0];
    const int* mask = (const int*)  d_in[1];
    const float* Wq = (const float*)d_in[2];
    const float* bq = (const float*)d_in[3];
    const float* Wk = (const float*)d_in[4];
    const float* bk = (const float*)d_in[5];
    const float* Wv = (const float*)d_in[6];
    const float* bv = (const float*)d_in[7];
    float* out = (float*)d_out;

    dim3 gproj(NC/128, (NB*NT)/128, 3);
    qkv_proj<<<gproj, 256>>>(x, Wq, bq, Wk, bk, Wv, bv);

    const int smem_bytes = 26432 * 4;   // 105728
    cudaFuncSetAttribute(attn_kernel,
                         cudaFuncAttributeMaxDynamicSharedMemorySize, smem_bytes);
    attn_kernel<<<dim3(NT/128, NB*NH), 256, smem_bytes>>>(mask, out);
}

// round 4
// speedup vs baseline: 3.2467x; 1.4536x over previous
#include <cuda_runtime.h>
#include <cstdint>

#define NB 4
#define NT 2048
#define NC 1024
#define NH 16
#define ND 64

// Scratch: Q,K,V in [B,H,T,D] layout (device globals: allocation-free).
__device__ float g_q[NB*NH*NT*ND];
__device__ float g_k[NB*NH*NT*ND];
__device__ float g_v[NB*NH*NT*ND];

// ---------------------------------------------------------------------------
// helpers: tf32 round-to-nearest, f32 bit view, m16n8k8 tf32 mma
// ---------------------------------------------------------------------------
__device__ __forceinline__ float tf32r(float x) {
    uint32_t u;
    asm("cvt.rna.tf32.f32 %0, %1;" : "=r"(u) : "f"(x));
    return __uint_as_float(u);
}
__device__ __forceinline__ uint32_t fau(float x) { return __float_as_uint(x); }

__device__ __forceinline__ void mma_tf32(float d[4], const uint32_t a[4],
                                         const uint32_t b[2]) {
    asm volatile(
        "mma.sync.aligned.m16n8k8.row.col.f32.tf32.tf32.f32 "
        "{%0,%1,%2,%3}, {%4,%5,%6,%7}, {%8,%9}, {%0,%1,%2,%3};"
        : "+f"(d[0]), "+f"(d[1]), "+f"(d[2]), "+f"(d[3])
        : "r"(a[0]), "r"(a[1]), "r"(a[2]), "r"(a[3]), "r"(b[0]), "r"(b[1]));
}

// ---------------------------------------------------------------------------
// QKV projection on tf32 tensor cores with split-activation compensation:
//   x = x_hi + x_lo (both tf32); acc += x_hi*W + x_lo*W  (W single tf32 round)
// grid = (NC/128, (NB*NT)/128, 3), block = 256 (8 warps: 2 m x 4 n).
// Block tile 128x128, BK=32. Warp tile 64x32 (4 m16 x 4 n8 mma tiles).
// ---------------------------------------------------------------------------
#define AST 36   // smem row stride: fragment LDS bank = (4g+c)%32, conflict-free

__global__ __launch_bounds__(256) void qkv_mma(
    const float* __restrict__ x,
    const float* __restrict__ Wq, const float* __restrict__ bq,
    const float* __restrict__ Wk, const float* __restrict__ bk,
    const float* __restrict__ Wv, const float* __restrict__ bv)
{
    extern __shared__ float smq[];
    float* Ah = smq;               // [128][AST] x_hi
    float* Al = smq + 128*AST;     // [128][AST] x_lo
    float* Bs = smq + 2*128*AST;   // [128][AST] W (tf32)

    const int z = blockIdx.z;
    const float* __restrict__ W    = (z == 0) ? Wq : ((z == 1) ? Wk : Wv);
    const float* __restrict__ bias = (z == 0) ? bq : ((z == 1) ? bk : bv);
    float* __restrict__ dst        = (z == 0) ? g_q : ((z == 1) ? g_k : g_v);
    const float scale = (z == 0) ? 0.125f : 1.0f;   // q pre-scaled by 1/sqrt(D)

    const int tid  = threadIdx.x;
    const int warp = tid >> 5;
    const int lane = tid & 31;
    const int g    = lane >> 2;
    const int c    = lane & 3;
    const int mw   = (warp & 1) * 64;    // warp m-base within block
    const int nw   = (warp >> 1) * 32;   // warp n-base within block

    const int m0 = blockIdx.y * 128;
    const int n0 = blockIdx.x * 128;

    // staging address: thread -> (row, 4-col) of the 128x32 tile
    const int srow = tid >> 3;
    const int sc4  = (tid & 7) * 4;

    float acc[4][4][4] = {};   // [mt][nt][reg]

    for (int k0 = 0; k0 < NC; k0 += 32) {
        // prefetch to registers (gmem latency overlapped with prior math)
        float4 xv[4], wv[4];
        #pragma unroll
        for (int p = 0; p < 4; p++) {
            xv[p] = *(const float4*)&x[(m0 + srow + 32*p)*NC + k0 + sc4];
            wv[p] = *(const float4*)&W[(n0 + srow + 32*p)*NC + k0 + sc4];
        }
        __syncthreads();
        #pragma unroll
        for (int p = 0; p < 4; p++) {
            const int r = srow + 32*p;
            float4 hi = make_float4(tf32r(xv[p].x), tf32r(xv[p].y),
                                    tf32r(xv[p].z), tf32r(xv[p].w));
            float4 lo = make_float4(tf32r(xv[p].x - hi.x), tf32r(xv[p].y - hi.y),
                                    tf32r(xv[p].z - hi.z), tf32r(xv[p].w - hi.w));
            *(float4*)&Ah[r*AST + sc4] = hi;
            *(float4*)&Al[r*AST + sc4] = lo;
            *(float4*)&Bs[r*AST + sc4] =
                make_float4(tf32r(wv[p].x), tf32r(wv[p].y),
                            tf32r(wv[p].z), tf32r(wv[p].w));
        }
        __syncthreads();

        #pragma unroll
        for (int kc = 0; kc < 4; kc++) {
            const int k = kc * 8;
            uint32_t bf[4][2];
            #pragma unroll
            for (int nt = 0; nt < 4; nt++) {
                const float* br = &Bs[(nw + nt*8 + g)*AST + k];
                bf[nt][0] = fau(br[c]);
                bf[nt][1] = fau(br[c + 4]);
            }
            #pragma unroll
            for (int mt = 0; mt < 4; mt++) {
                const float* ar = &Ah[(mw + mt*16 + g)*AST + k];
                const float* lr = &Al[(mw + mt*16 + g)*AST + k];
                uint32_t ah[4] = {fau(ar[c]), fau(ar[8*AST + c]),
                                  fau(ar[c + 4]), fau(ar[8*AST + c + 4])};
                uint32_t al[4] = {fau(lr[c]), fau(lr[8*AST + c]),
                                  fau(lr[c + 4]), fau(lr[8*AST + c + 4])};
                #pragma unroll
                for (int nt = 0; nt < 4; nt++) {
                    mma_tf32(acc[mt][nt], ah, bf[nt]);
                    mma_tf32(acc[mt][nt], al, bf[nt]);
                }
            }
        }
    }

    // Epilogue: bias + scale (fp32), scatter to [B,H,T,D]
    #pragma unroll
    for (int nt = 0; nt < 4; nt++) {
        const int col = n0 + nw + nt*8 + 2*c;
        float2 b2 = *(const float2*)&bias[col];
        const int h  = col >> 6;
        const int cc = col & 63;
        #pragma unroll
        for (int mt = 0; mt < 4; mt++) {
            #pragma unroll
            for (int rh = 0; rh < 2; rh++) {
                const int m = m0 + mw + mt*16 + g + rh*8;
                const int b = m >> 11;
                const int t = m & (NT - 1);
                float2 o;
                o.x = (acc[mt][nt][rh*2 + 0] + b2.x) * scale;
                o.y = (acc[mt][nt][rh*2 + 1] + b2.y) * scale;
                *(float2*)&dst[((b*NH + h)*NT + t)*ND + cc] = o;
            }
        }
    }
}

// ---------------------------------------------------------------------------
// Flash attention on tf32 tensor cores (unchanged from R3).
// grid = (NT/128, NB*NH), block = 256 (8 warps, 16 q-rows each).
// ---------------------------------------------------------------------------
#define QP 68
#define VP 72

__global__ __launch_bounds__(256) void attn_kernel(
    const int* __restrict__ mask, float* __restrict__ out)
{
    extern __shared__ float sm[];
    float* Qs    = sm;              // [128][QP] = 8704
    float* Ps    = sm + 8704;       // [128][QP] = 8704
    float* Ks    = sm + 17408;      // [64][QP]  = 4352
    float* Vs    = sm + 21760;      // [64][VP]  = 4608
    float* maskf = sm + 26368;      // [64]

    const int tid  = threadIdx.x;
    const int warp = tid >> 5;
    const int lane = tid & 31;
    const int g    = lane >> 2;
    const int c    = lane & 3;
    const int wr   = warp * 16;

    const int bh = blockIdx.y;
    const int b  = bh >> 4;
    const int h  = bh & 15;
    const int q0 = blockIdx.x * 128;

    const float* __restrict__ qb = g_q + (bh*NT + q0) * ND;
    const float* __restrict__ kb = g_k + bh*NT*ND;
    const float* __restrict__ vb = g_v + bh*NT*ND;
    const int*   __restrict__ mb = mask + b*NT;

    #pragma unroll
    for (int i = 0; i < 8; i++) {
        int fi = tid + 256*i;
        int row = fi >> 4, c4 = (fi & 15) * 4;
        float4 v = *(const float4*)&qb[row*ND + c4];
        *(float4*)&Qs[row*QP + c4] =
            make_float4(tf32r(v.x), tf32r(v.y), tf32r(v.z), tf32r(v.w));
    }

    float o[8][4] = {};
    float m_run[2] = {-1e30f, -1e30f};
    float l_run[2] = {0.f, 0.f};

    for (int k0 = 0; k0 < NT; k0 += 64) {
        __syncthreads();
        #pragma unroll
        for (int i = 0; i < 4; i++) {
            int fi = tid + 256*i;
            int row = fi >> 4, c4 = (fi & 15) * 4;
            float4 v = *(const float4*)&kb[(k0 + row)*ND + c4];
            *(float4*)&Ks[row*QP + c4] =
                make_float4(tf32r(v.x), tf32r(v.y), tf32r(v.z), tf32r(v.w));
            float4 u = *(const float4*)&vb[(k0 + row)*ND + c4];
            *(float4*)&Vs[row*VP + c4] =
                make_float4(tf32r(u.x), tf32r(u.y), tf32r(u.z), tf32r(u.w));
        }
        if (tid < 64) maskf[tid] = (mb[k0 + tid] > 0) ? 0.0f : -1e30f;
        __syncthreads();

        float s[8][4] = {};
        #pragma unroll
        for (int kt = 0; kt < 8; kt++) {
            const int k = kt*8;
            uint32_t a[4];
            const float* qr = &Qs[(wr + g)*QP + k];
            a[0] = fau(qr[c]);          a[1] = fau(qr[8*QP + c]);
            a[2] = fau(qr[c + 4]);      a[3] = fau(qr[8*QP + c + 4]);
            #pragma unroll
            for (int nt = 0; nt < 8; nt++) {
                uint32_t bb[2];
                const float* kr = &Ks[(nt*8 + g)*QP + k];
                bb[0] = fau(kr[c]); bb[1] = fau(kr[c + 4]);
                mma_tf32(s[nt], a, bb);
            }
        }

        #pragma unroll
        for (int nt = 0; nt < 8; nt++) {
            float2 mf = *(const float2*)&maskf[nt*8 + 2*c];
            s[nt][0] += mf.x; s[nt][1] += mf.y;
            s[nt][2] += mf.x; s[nt][3] += mf.y;
        }

        float alpha[2];
        #pragma unroll
        for (int rh = 0; rh < 2; rh++) {
            float rm = -1e30f;
            #pragma unroll
            for (int nt = 0; nt < 8; nt++)
                rm = fmaxf(rm, fmaxf(s[nt][rh*2], s[nt][rh*2+1]));
            rm = fmaxf(rm, __shfl_xor_sync(0xffffffffu, rm, 1));
            rm = fmaxf(rm, __shfl_xor_sync(0xffffffffu, rm, 2));
            float mnew = fmaxf(m_run[rh], rm);
            alpha[rh] = __expf(m_run[rh] - mnew);
            m_run[rh] = mnew;
            float rs = 0.f;
            #pragma unroll
            for (int nt = 0; nt < 8; nt++) {
                float p0 = __expf(s[nt][rh*2]   - mnew);
                float p1 = __expf(s[nt][rh*2+1] - mnew);
                s[nt][rh*2] = p0; s[nt][rh*2+1] = p1;
                rs += p0 + p1;
            }
            rs += __shfl_xor_sync(0xffffffffu, rs, 1);
            rs += __shfl_xor_sync(0xffffffffu, rs, 2);
            l_run[rh] = l_run[rh]*alpha[rh] + rs;
        }

        #pragma unroll
        for (int nt = 0; nt < 8; nt++) {
            o[nt][0] *= alpha[0]; o[nt][1] *= alpha[0];
            o[nt][2] *= alpha[1]; o[nt][3] *= alpha[1];
        }

        #pragma unroll
        for (int nt = 0; nt < 8; nt++) {
            float2 lo = make_float2(tf32r(s[nt][0]), tf32r(s[nt][1]));
            float2 hi = make_float2(tf32r(s[nt][2]), tf32r(s[nt][3]));
            *(float2*)&Ps[(wr + g    )*QP + nt*8 + 2*c] = lo;
            *(float2*)&Ps[(wr + g + 8)*QP + nt*8 + 2*c] = hi;
        }
        __syncwarp();

        #pragma unroll
        for (int kt = 0; kt < 8; kt++) {
            const int k = kt*8;
            uint32_t a[4];
            const float* pr = &Ps[(wr + g)*QP + k];
            a[0] = fau(pr[c]);          a[1] = fau(pr[8*QP + c]);
            a[2] = fau(pr[c + 4]);      a[3] = fau(pr[8*QP + c + 4]);
            #pragma unroll
            for (int nt = 0; nt < 8; nt++) {
                uint32_t bb[2];
                bb[0] = fau(Vs[(k + c    )*VP + nt*8 + g]);
                bb[1] = fau(Vs[(k + c + 4)*VP + nt*8 + g]);
                mma_tf32(o[nt], a, bb);
            }
        }
    }

    const float inv0 = 1.0f / l_run[0];
    const float inv1 = 1.0f / l_run[1];
    const int t0 = q0 + wr + g;
    float* ob0 = out + (b*NT + t0    )*NC + h*ND;
    float* ob1 = out + (b*NT + t0 + 8)*NC + h*ND;
    #pragma unroll
    for (int nt = 0; nt < 8; nt++) {
        *(float2*)&ob0[nt*8 + 2*c] = make_float2(o[nt][0]*inv0, o[nt][1]*inv0);
        *(float2*)&ob1[nt*8 + 2*c] = make_float2(o[nt][2]*inv1, o[nt][3]*inv1);
    }
}

// ---------------------------------------------------------------------------
extern "C" void kernel_launch(void* const* d_in, const int* in_sizes, int n_in,
                              void* d_out, int out_size)
{
    const float* x  = (const float*)d_in[0];
    const int* mask = (const int*)  d_in[1];
    const float* Wq = (const float*)d_in[2];
    const float* bq = (const float*)d_in[3];
    const float* Wk = (const float*)d_in[4];
    const float* bk = (const float*)d_in[5];
    const float* Wv = (const float*)d_in[6];
    const float* bv = (const float*)d_in[7];
    float* out = (float*)d_out;

    const int qkv_smem = 3 * 128 * AST * 4;   // 55296
    cudaFuncSetAttribute(qkv_mma,
                         cudaFuncAttributeMaxDynamicSharedMemorySize, qkv_smem);
    qkv_mma<<<dim3(NC/128, (NB*NT)/128, 3), 256, qkv_smem>>>(
        x, Wq, bq, Wk, bk, Wv, bv);

    const int attn_smem = 26432 * 4;          // 105728
    cudaFuncSetAttribute(attn_kernel,
                         cudaFuncAttributeMaxDynamicSharedMemorySize, attn_smem);
    attn_kernel<<<dim3(NT/128, NB*NH), 256, attn_smem>>>(mask, out);
}

// round 5
// speedup vs baseline: 3.4129x; 1.0512x over previous
#include <cuda_runtime.h>
#include <cstdint>

#define NB 4
#define NT 2048
#define NC 1024
#define NH 16
#define ND 64

// Scratch: Q,K,V in [B,H,T,D] layout (device globals: allocation-free).
__device__ float g_q[NB*NH*NT*ND];
__device__ float g_k[NB*NH*NT*ND];
__device__ float g_v[NB*NH*NT*ND];

// ---------------------------------------------------------------------------
// helpers: tf32 round-to-nearest, f32 bit view, m16n8k8 tf32 mma
// ---------------------------------------------------------------------------
__device__ __forceinline__ float tf32r(float x) {
    uint32_t u;
    asm("cvt.rna.tf32.f32 %0, %1;" : "=r"(u) : "f"(x));
    return __uint_as_float(u);
}
__device__ __forceinline__ uint32_t fau(float x) { return __float_as_uint(x); }

__device__ __forceinline__ void mma_tf32(float d[4], const uint32_t a[4],
                                         const uint32_t b[2]) {
    asm volatile(
        "mma.sync.aligned.m16n8k8.row.col.f32.tf32.tf32.f32 "
        "{%0,%1,%2,%3}, {%4,%5,%6,%7}, {%8,%9}, {%0,%1,%2,%3};"
        : "+f"(d[0]), "+f"(d[1]), "+f"(d[2]), "+f"(d[3])
        : "r"(a[0]), "r"(a[1]), "r"(a[2]), "r"(a[3]), "r"(b[0]), "r"(b[1]));
}

// ---------------------------------------------------------------------------
// QKV projection on tf32 tensor cores with split-activation compensation
// (unchanged from R4).
// ---------------------------------------------------------------------------
#define AST 36

__global__ __launch_bounds__(256) void qkv_mma(
    const float* __restrict__ x,
    const float* __restrict__ Wq, const float* __restrict__ bq,
    const float* __restrict__ Wk, const float* __restrict__ bk,
    const float* __restrict__ Wv, const float* __restrict__ bv)
{
    extern __shared__ float smq[];
    float* Ah = smq;
    float* Al = smq + 128*AST;
    float* Bs = smq + 2*128*AST;

    const int z = blockIdx.z;
    const float* __restrict__ W    = (z == 0) ? Wq : ((z == 1) ? Wk : Wv);
    const float* __restrict__ bias = (z == 0) ? bq : ((z == 1) ? bk : bv);
    float* __restrict__ dst        = (z == 0) ? g_q : ((z == 1) ? g_k : g_v);
    const float scale = (z == 0) ? 0.125f : 1.0f;

    const int tid  = threadIdx.x;
    const int warp = tid >> 5;
    const int lane = tid & 31;
    const int g    = lane >> 2;
    const int c    = lane & 3;
    const int mw   = (warp & 1) * 64;
    const int nw   = (warp >> 1) * 32;

    const int m0 = blockIdx.y * 128;
    const int n0 = blockIdx.x * 128;

    const int srow = tid >> 3;
    const int sc4  = (tid & 7) * 4;

    float acc[4][4][4] = {};

    for (int k0 = 0; k0 < NC; k0 += 32) {
        float4 xv[4], wv[4];
        #pragma unroll
        for (int p = 0; p < 4; p++) {
            xv[p] = *(const float4*)&x[(m0 + srow + 32*p)*NC + k0 + sc4];
            wv[p] = *(const float4*)&W[(n0 + srow + 32*p)*NC + k0 + sc4];
        }
        __syncthreads();
        #pragma unroll
        for (int p = 0; p < 4; p++) {
            const int r = srow + 32*p;
            float4 hi = make_float4(tf32r(xv[p].x), tf32r(xv[p].y),
                                    tf32r(xv[p].z), tf32r(xv[p].w));
            float4 lo = make_float4(tf32r(xv[p].x - hi.x), tf32r(xv[p].y - hi.y),
                                    tf32r(xv[p].z - hi.z), tf32r(xv[p].w - hi.w));
            *(float4*)&Ah[r*AST + sc4] = hi;
            *(float4*)&Al[r*AST + sc4] = lo;
            *(float4*)&Bs[r*AST + sc4] =
                make_float4(tf32r(wv[p].x), tf32r(wv[p].y),
                            tf32r(wv[p].z), tf32r(wv[p].w));
        }
        __syncthreads();

        #pragma unroll
        for (int kc = 0; kc < 4; kc++) {
            const int k = kc * 8;
            uint32_t bf[4][2];
            #pragma unroll
            for (int nt = 0; nt < 4; nt++) {
                const float* br = &Bs[(nw + nt*8 + g)*AST + k];
                bf[nt][0] = fau(br[c]);
                bf[nt][1] = fau(br[c + 4]);
            }
            #pragma unroll
            for (int mt = 0; mt < 4; mt++) {
                const float* ar = &Ah[(mw + mt*16 + g)*AST + k];
                const float* lr = &Al[(mw + mt*16 + g)*AST + k];
                uint32_t ah[4] = {fau(ar[c]), fau(ar[8*AST + c]),
                                  fau(ar[c + 4]), fau(ar[8*AST + c + 4])};
                uint32_t al[4] = {fau(lr[c]), fau(lr[8*AST + c]),
                                  fau(lr[c + 4]), fau(lr[8*AST + c + 4])};
                #pragma unroll
                for (int nt = 0; nt < 4; nt++) {
                    mma_tf32(acc[mt][nt], ah, bf[nt]);
                    mma_tf32(acc[mt][nt], al, bf[nt]);
                }
            }
        }
    }

    #pragma unroll
    for (int nt = 0; nt < 4; nt++) {
        const int col = n0 + nw + nt*8 + 2*c;
        float2 b2 = *(const float2*)&bias[col];
        const int h  = col >> 6;
        const int cc = col & 63;
        #pragma unroll
        for (int mt = 0; mt < 4; mt++) {
            #pragma unroll
            for (int rh = 0; rh < 2; rh++) {
                const int m = m0 + mw + mt*16 + g + rh*8;
                const int b = m >> 11;
                const int t = m & (NT - 1);
                float2 o;
                o.x = (acc[mt][nt][rh*2 + 0] + b2.x) * scale;
                o.y = (acc[mt][nt][rh*2 + 1] + b2.y) * scale;
                *(float2*)&dst[((b*NH + h)*NT + t)*ND + cc] = o;
            }
        }
    }
}

// ---------------------------------------------------------------------------
// Flash attention on tf32 tensor cores.
// R5: 4 warps x 32 q-rows (two m16 tiles per warp) -> each K/V b-fragment
// feeds TWO mmas, halving dominant smem traffic per unit work.
// grid = (NT/128, NB*NH), block = 128.
// ---------------------------------------------------------------------------
#define QP 68
#define VP 72

__global__ __launch_bounds__(128) void attn_kernel(
    const int* __restrict__ mask, float* __restrict__ out)
{
    extern __shared__ float sm[];
    float* Qs    = sm;              // [128][QP] = 8704
    float* Ps    = sm + 8704;       // [128][QP] = 8704
    float* Ks    = sm + 17408;      // [64][QP]  = 4352
    float* Vs    = sm + 21760;      // [64][VP]  = 4608
    float* maskf = sm + 26368;      // [64]

    const int tid  = threadIdx.x;
    const int warp = tid >> 5;      // 0..3
    const int lane = tid & 31;
    const int g    = lane >> 2;
    const int c    = lane & 3;
    const int wr   = warp * 32;     // warp's q-row base (32 rows per warp)

    const int bh = blockIdx.y;
    const int b  = bh >> 4;
    const int h  = bh & 15;
    const int q0 = blockIdx.x * 128;

    const float* __restrict__ qb = g_q + (bh*NT + q0) * ND;
    const float* __restrict__ kb = g_k + bh*NT*ND;
    const float* __restrict__ vb = g_v + bh*NT*ND;
    const int*   __restrict__ mb = mask + b*NT;

    // Stage Q once (tf32-rounded): 128 rows x 64 d, 16 float4 per thread
    #pragma unroll
    for (int i = 0; i < 16; i++) {
        int fi = tid + 128*i;
        int row = fi >> 4, c4 = (fi & 15) * 4;
        float4 v = *(const float4*)&qb[row*ND + c4];
        *(float4*)&Qs[row*QP + c4] =
            make_float4(tf32r(v.x), tf32r(v.y), tf32r(v.z), tf32r(v.w));
    }

    float o[2][8][4] = {};
    float m_run[2][2] = {{-1e30f,-1e30f},{-1e30f,-1e30f}};
    float l_run[2][2] = {{0.f,0.f},{0.f,0.f}};

    for (int k0 = 0; k0 < NT; k0 += 64) {
        __syncthreads();
        #pragma unroll
        for (int i = 0; i < 8; i++) {
            int fi = tid + 128*i;
            int row = fi >> 4, c4 = (fi & 15) * 4;
            float4 v = *(const float4*)&kb[(k0 + row)*ND + c4];
            *(float4*)&Ks[row*QP + c4] =
                make_float4(tf32r(v.x), tf32r(v.y), tf32r(v.z), tf32r(v.w));
            float4 u = *(const float4*)&vb[(k0 + row)*ND + c4];
            *(float4*)&Vs[row*VP + c4] =
                make_float4(tf32r(u.x), tf32r(u.y), tf32r(u.z), tf32r(u.w));
        }
        if (tid < 64) maskf[tid] = (mb[k0 + tid] > 0) ? 0.0f : -1e30f;
        __syncthreads();

        // ---- S = Q @ K^T  (per warp: 2 x 16 rows x 64 keys) ----
        float s[2][8][4] = {};
        #pragma unroll
        for (int kt = 0; kt < 8; kt++) {
            const int k = kt*8;
            uint32_t a[2][4];
            #pragma unroll
            for (int mt = 0; mt < 2; mt++) {
                const float* qr = &Qs[(wr + mt*16 + g)*QP + k];
                a[mt][0] = fau(qr[c]);       a[mt][1] = fau(qr[8*QP + c]);
                a[mt][2] = fau(qr[c + 4]);   a[mt][3] = fau(qr[8*QP + c + 4]);
            }
            #pragma unroll
            for (int nt = 0; nt < 8; nt++) {
                uint32_t bb[2];
                const float* kr = &Ks[(nt*8 + g)*QP + k];
                bb[0] = fau(kr[c]); bb[1] = fau(kr[c + 4]);
                mma_tf32(s[0][nt], a[0], bb);   // b-fragment reused 2x
                mma_tf32(s[1][nt], a[1], bb);
            }
        }

        // additive mask
        #pragma unroll
        for (int nt = 0; nt < 8; nt++) {
            float2 mf = *(const float2*)&maskf[nt*8 + 2*c];
            #pragma unroll
            for (int mt = 0; mt < 2; mt++) {
                s[mt][nt][0] += mf.x; s[mt][nt][1] += mf.y;
                s[mt][nt][2] += mf.x; s[mt][nt][3] += mf.y;
            }
        }

        // ---- online softmax (per mt, per row-half) ----
        #pragma unroll
        for (int mt = 0; mt < 2; mt++) {
            float alpha[2];
            #pragma unroll
            for (int rh = 0; rh < 2; rh++) {
                float rm = -1e30f;
                #pragma unroll
                for (int nt = 0; nt < 8; nt++)
                    rm = fmaxf(rm, fmaxf(s[mt][nt][rh*2], s[mt][nt][rh*2+1]));
                rm = fmaxf(rm, __shfl_xor_sync(0xffffffffu, rm, 1));
                rm = fmaxf(rm, __shfl_xor_sync(0xffffffffu, rm, 2));
                float mnew = fmaxf(m_run[mt][rh], rm);
                alpha[rh] = __expf(m_run[mt][rh] - mnew);
                m_run[mt][rh] = mnew;
                float rs = 0.f;
                #pragma unroll
                for (int nt = 0; nt < 8; nt++) {
                    float p0 = __expf(s[mt][nt][rh*2]   - mnew);
                    float p1 = __expf(s[mt][nt][rh*2+1] - mnew);
                    s[mt][nt][rh*2] = p0; s[mt][nt][rh*2+1] = p1;
                    rs += p0 + p1;
                }
                rs += __shfl_xor_sync(0xffffffffu, rs, 1);
                rs += __shfl_xor_sync(0xffffffffu, rs, 2);
                l_run[mt][rh] = l_run[mt][rh]*alpha[rh] + rs;
            }
            #pragma unroll
            for (int nt = 0; nt < 8; nt++) {
                o[mt][nt][0] *= alpha[0]; o[mt][nt][1] *= alpha[0];
                o[mt][nt][2] *= alpha[1]; o[mt][nt][3] *= alpha[1];
            }
            // P -> smem (tf32), rows wr+mt*16+g / +8
            #pragma unroll
            for (int nt = 0; nt < 8; nt++) {
                float2 lo = make_float2(tf32r(s[mt][nt][0]), tf32r(s[mt][nt][1]));
                float2 hi = make_float2(tf32r(s[mt][nt][2]), tf32r(s[mt][nt][3]));
                *(float2*)&Ps[(wr + mt*16 + g    )*QP + nt*8 + 2*c] = lo;
                *(float2*)&Ps[(wr + mt*16 + g + 8)*QP + nt*8 + 2*c] = hi;
            }
        }
        __syncwarp();

        // ---- O += P @ V ----
        #pragma unroll
        for (int kt = 0; kt < 8; kt++) {
            const int k = kt*8;
            uint32_t a[2][4];
            #pragma unroll
            for (int mt = 0; mt < 2; mt++) {
                const float* pr = &Ps[(wr + mt*16 + g)*QP + k];
                a[mt][0] = fau(pr[c]);       a[mt][1] = fau(pr[8*QP + c]);
                a[mt][2] = fau(pr[c + 4]);   a[mt][3] = fau(pr[8*QP + c + 4]);
            }
            #pragma unroll
            for (int nt = 0; nt < 8; nt++) {
                uint32_t bb[2];
                bb[0] = fau(Vs[(k + c    )*VP + nt*8 + g]);
                bb[1] = fau(Vs[(k + c + 4)*VP + nt*8 + g]);
                mma_tf32(o[0][nt], a[0], bb);   // b-fragment reused 2x
                mma_tf32(o[1][nt], a[1], bb);
            }
        }
    }

    // epilogue
    #pragma unroll
    for (int mt = 0; mt < 2; mt++) {
        const float inv0 = 1.0f / l_run[mt][0];
        const float inv1 = 1.0f / l_run[mt][1];
        const int t0 = q0 + wr + mt*16 + g;
        float* ob0 = out + (b*NT + t0    )*NC + h*ND;
        float* ob1 = out + (b*NT + t0 + 8)*NC + h*ND;
        #pragma unroll
        for (int nt = 0; nt < 8; nt++) {
            *(float2*)&ob0[nt*8 + 2*c] =
                make_float2(o[mt][nt][0]*inv0, o[mt][nt][1]*inv0);
            *(float2*)&ob1[nt*8 + 2*c] =
                make_float2(o[mt][nt][2]*inv1, o[mt][nt][3]*inv1);
        }
    }
}

// ---------------------------------------------------------------------------
extern "C" void kernel_launch(void* const* d_in, const int* in_sizes, int n_in,
                              void* d_out, int out_size)
{
    const float* x  = (const float*)d_in[0];
    const int* mask = (const int*)  d_in[1];
    const float* Wq = (const float*)d_in[2];
    const float* bq = (const float*)d_in[3];
    const float* Wk = (const float*)d_in[4];
    const float* bk = (const float*)d_in[5];
    const float* Wv = (const float*)d_in[6];
    const float* bv = (const float*)d_in[7];
    float* out = (float*)d_out;

    const int qkv_smem = 3 * 128 * AST * 4;   // 55296
    cudaFuncSetAttribute(qkv_mma,
                         cudaFuncAttributeMaxDynamicSharedMemorySize, qkv_smem);
    qkv_mma<<<dim3(NC/128, (NB*NT)/128, 3), 256, qkv_smem>>>(
        x, Wq, bq, Wk, bk, Wv, bv);

    const int attn_smem = 26432 * 4;          // 105728
    cudaFuncSetAttribute(attn_kernel,
                         cudaFuncAttributeMaxDynamicSharedMemorySize, attn_smem);
    attn_kernel<<<dim3(NT/128, NB*NH), 128, attn_smem>>>(mask, out);
}